// round 5
// baseline (speedup 1.0000x reference)
#include <cuda_runtime.h>
#include <cuda_bf16.h>
#include <cstdint>
#include <cfloat>

// KeyValueBottleneck: b=32, C=64, n=64, dk=dv=16, J=1024
// out = concat(qv[2097152], new_keys[1048576], new_cluster_size[65536], new_keys_avg[1048576])

#define DECAY 0.95f
#define OMD   0.05f
#define EPSV  1e-5f

constexpr int Cc = 64, Nn = 64, DK = 16, J = 1024, PPC = 2048, NPTS = Cc * PPC;
constexpr int OFF_QV   = 0;
constexpr int OFF_KEYS = 2097152;
constexpr int OFF_CS   = OFF_KEYS + Cc * J * DK;  // 3145728
constexpr int OFF_KA   = OFF_CS + Cc * J;         // 3211264

// ---------------- scratch (device globals; no allocation) --------------------
__device__ __nv_bfloat16 g_xa[(size_t)NPTS * 32];   // 8 MB: [xhi(16) | xlo(16)]
__device__ __nv_bfloat16 g_kb[(size_t)Cc * J * 32]; // 4 MB: [k(16) | k(16)]
__device__ float    g_kk[Cc * J];                   // -0.5*||k||^2 (fp32, exact bias)
__device__ float    g_xn[NPTS];                     // ||x|| per point
__device__ unsigned g_km[Cc];                       // max ||k|| per channel (bits)

__device__ __forceinline__ uint32_t pkbf(float a, float b) {
    __nv_bfloat16 ha = __float2bfloat16(a), hb = __float2bfloat16(b);
    return (uint32_t)__bfloat16_as_ushort(ha) | ((uint32_t)__bfloat16_as_ushort(hb) << 16);
}

// classic tensor-core MMA: m16n8k16, bf16 x bf16 -> fp32 (sm_80+, works on sm_100)
__device__ __forceinline__ void mma16816(float* d, const uint32_t* a, const uint32_t* b) {
    asm volatile(
        "mma.sync.aligned.m16n8k16.row.col.f32.bf16.bf16.f32 "
        "{%0,%1,%2,%3}, {%4,%5,%6,%7}, {%8,%9}, {%0,%1,%2,%3};"
        : "+f"(d[0]), "+f"(d[1]), "+f"(d[2]), "+f"(d[3])
        : "r"(a[0]), "r"(a[1]), "r"(a[2]), "r"(a[3]), "r"(b[0]), "r"(b[1]));
}

// ---------------- kernel 0: prep (bf16 split convert + bias + EMA seed) ------
__global__ __launch_bounds__(128) void k_prep(const float* __restrict__ x,
                                              const float* __restrict__ keys,
                                              const float* __restrict__ keys_avg,
                                              const float* __restrict__ cs,
                                              float* __restrict__ out) {
    const int tid = blockIdx.x * 128 + threadIdx.x;  // 0..131071

    // EMA seed: out_ka = DECAY*keys_avg ; out_cs = DECAY*cluster_size
    {
        const float4* ka4 = (const float4*)keys_avg;
        float4* o4 = (float4*)out;
        float4 v = ka4[tid];
        v.x *= DECAY; v.y *= DECAY; v.z *= DECAY; v.w *= DECAY;
        o4[OFF_KA / 4 + tid] = v;
        float4 w = ka4[tid + 131072];
        w.x *= DECAY; w.y *= DECAY; w.z *= DECAY; w.w *= DECAY;
        o4[OFF_KA / 4 + tid + 131072] = w;
        if (tid < (Cc * J) / 4) {
            float4 u = ((const float4*)cs)[tid];
            u.x *= DECAY; u.y *= DECAY; u.z *= DECAY; u.w *= DECAY;
            o4[OFF_CS / 4 + tid] = u;
        }
    }

    // X row -> g_xa  (row-major points within channel: tid = c*2048 + i)
    {
        int c = tid >> 11, i = tid & 2047;
        int bb = i >> 6, ni = i & 63;
        const float* xr = x + (size_t)((bb * Cc + c) * Nn + ni) * DK;
        float hi[16], lo[16], n2 = 0.f;
#pragma unroll
        for (int d = 0; d < 16; d++) {
            float v = xr[d];
            n2 += v * v;
            float h = __bfloat162float(__float2bfloat16(v));
            hi[d] = v; lo[d] = v - h;
        }
        uint32_t w[16];
#pragma unroll
        for (int d = 0; d < 8; d++) {
            w[d]     = pkbf(hi[2 * d], hi[2 * d + 1]);
            w[8 + d] = pkbf(lo[2 * d], lo[2 * d + 1]);
        }
        uint4* dst = (uint4*)(g_xa + (size_t)tid * 32);
#pragma unroll
        for (int q = 0; q < 4; q++)
            dst[q] = make_uint4(w[4 * q], w[4 * q + 1], w[4 * q + 2], w[4 * q + 3]);
        g_xn[tid] = sqrtf(n2);
    }

    // Key row -> g_kb + bias + per-channel kmax
    if (tid < Cc * J) {
        int kc = tid >> 10;
        const float* kr = keys + (size_t)tid * DK;
        float kv[16], kk = 0.f;
#pragma unroll
        for (int d = 0; d < 16; d++) { float v = kr[d]; kv[d] = v; kk += v * v; }
        uint32_t w[16];
#pragma unroll
        for (int d = 0; d < 8; d++) {
            uint32_t p = pkbf(kv[2 * d], kv[2 * d + 1]);
            w[d] = p; w[8 + d] = p;
        }
        uint4* dst = (uint4*)(g_kb + (size_t)tid * 32);
#pragma unroll
        for (int q = 0; q < 4; q++)
            dst[q] = make_uint4(w[4 * q], w[4 * q + 1], w[4 * q + 2], w[4 * q + 3]);
        g_kk[tid] = -0.5f * kk;
        atomicMax(&g_km[kc], __float_as_uint(sqrtf(kk)));
    }
}

// ---------------- kernel 1: HMMA screening + exact fp32 fallback -------------
// grid = 1024 CTAs (c = bid>>4, mt = bid&15), 128 threads (4 warps).
// CTA: 128 points x 1024 keys. Warp w owns rows [w*32, w*32+32).
// Screen score s = (xhi+xlo)(.)k_bf16 (fp32 accum) + exact fp32 bias(-0.5kk).
__global__ __launch_bounds__(128) void k_screen(const float* __restrict__ x,
                                                const float* __restrict__ keys,
                                                const float* __restrict__ values,
                                                float* __restrict__ out) {
    // 80-byte padded rows -> conflict-free fragment LDS (stride 20 banks)
    __shared__ __align__(16) unsigned char sA[128 * 80];    // 10240 B
    __shared__ __align__(16) unsigned char sB[256 * 80];    // 20480 B
    __shared__ float skk[J];                                // 4096 B
    __shared__ float sb1[128], sb2[128];
    __shared__ int   sbj[128];

    const int t = threadIdx.x, wid = t >> 5, lane = t & 31;
    const int c = blockIdx.x >> 4, mt = blockIdx.x & 15;
    const int lg = lane >> 2, lc = lane & 3;  // group-of-4 row id, col id

    // load A tile (128 rows x 64 B) into padded smem
    {
        const uint4* src = (const uint4*)(g_xa + (size_t)(c * PPC + mt * 128) * 32);
#pragma unroll
        for (int v = t; v < 512; v += 128) {
            int r = v >> 2, q = v & 3;
            *(uint4*)(sA + r * 80 + q * 16) = src[v];
        }
        const float4* kk4 = (const float4*)(g_kk + c * J);
        ((float4*)skk)[t]       = kk4[t];
        ((float4*)skk)[t + 128] = kk4[t + 128];
    }
    __syncthreads();

    // A fragments, register-resident: a[mtile][kstep][4]
    uint32_t afr[2][2][4];
#pragma unroll
    for (int m = 0; m < 2; m++)
#pragma unroll
        for (int ks = 0; ks < 2; ks++) {
            int r0 = wid * 32 + m * 16 + lg;
            int bo = ks * 32 + lc * 4;
            afr[m][ks][0] = *(const uint32_t*)(sA + r0 * 80 + bo);
            afr[m][ks][1] = *(const uint32_t*)(sA + (r0 + 8) * 80 + bo);
            afr[m][ks][2] = *(const uint32_t*)(sA + r0 * 80 + bo + 16);
            afr[m][ks][3] = *(const uint32_t*)(sA + (r0 + 8) * 80 + bo + 16);
        }

    // trackers: ti = m*2+h <-> row wid*32 + m*16 + h*8 + lg ; cols j === lc*2 (mod 8)
    float tb1[4] = {-FLT_MAX, -FLT_MAX, -FLT_MAX, -FLT_MAX};
    float tb2[4] = {-FLT_MAX, -FLT_MAX, -FLT_MAX, -FLT_MAX};
    int   tj[4]  = {0, 0, 0, 0};

    for (int ch = 0; ch < 4; ch++) {
        // load B chunk (256 keys x 64 B)
        const uint4* src = (const uint4*)(g_kb + (size_t)(c * J + ch * 256) * 32);
#pragma unroll
        for (int v = t; v < 1024; v += 128) {
            int r = v >> 2, q = v & 3;
            *(uint4*)(sB + r * 80 + q * 16) = src[v];
        }
        __syncthreads();

#pragma unroll 8
        for (int jt = 0; jt < 32; jt++) {
            const int jbase = ch * 256 + jt * 8;
            const unsigned char* brow = sB + (jt * 8 + lg) * 80;
            uint32_t b0[2], b1[2];
            b0[0] = *(const uint32_t*)(brow + lc * 4);
            b0[1] = *(const uint32_t*)(brow + lc * 4 + 16);
            b1[0] = *(const uint32_t*)(brow + 32 + lc * 4);
            b1[1] = *(const uint32_t*)(brow + 32 + lc * 4 + 16);

            float d0[4] = {0.f, 0.f, 0.f, 0.f}, d1[4] = {0.f, 0.f, 0.f, 0.f};
            mma16816(d0, afr[0][0], b0);
            mma16816(d0, afr[0][1], b1);
            mma16816(d1, afr[1][0], b0);
            mma16816(d1, afr[1][1], b1);

            const int j0 = jbase + lc * 2;
            const float bias0 = skk[j0], bias1 = skk[j0 + 1];

#define UPD(ti, val, jj) { float s_ = (val); \
    if (s_ > tb1[ti]) { tb2[ti] = tb1[ti]; tb1[ti] = s_; tj[ti] = (jj); } \
    else if (s_ > tb2[ti]) tb2[ti] = s_; }
            UPD(0, d0[0] + bias0, j0); UPD(0, d0[1] + bias1, j0 + 1);
            UPD(1, d0[2] + bias0, j0); UPD(1, d0[3] + bias1, j0 + 1);
            UPD(2, d1[0] + bias0, j0); UPD(2, d1[1] + bias1, j0 + 1);
            UPD(3, d1[2] + bias0, j0); UPD(3, d1[3] + bias1, j0 + 1);
#undef UPD
        }
        __syncthreads();
    }

    // merge across the 4 lanes of each row-quad (disjoint col classes)
#pragma unroll
    for (int mask = 1; mask <= 2; mask <<= 1) {
#pragma unroll
        for (int ti = 0; ti < 4; ti++) {
            float ob1 = __shfl_xor_sync(0xffffffffu, tb1[ti], mask);
            float ob2 = __shfl_xor_sync(0xffffffffu, tb2[ti], mask);
            int   oj  = __shfl_xor_sync(0xffffffffu, tj[ti],  mask);
            if (ob1 > tb1[ti] || (ob1 == tb1[ti] && oj < tj[ti])) {
                tb2[ti] = fmaxf(tb1[ti], ob2);
                tb1[ti] = ob1; tj[ti] = oj;
            } else {
                tb2[ti] = fmaxf(tb2[ti], ob1);
            }
        }
    }
    if (lc == 0) {
#pragma unroll
        for (int ti = 0; ti < 4; ti++) {
            int r = wid * 32 + (ti >> 1) * 16 + (ti & 1) * 8 + lg;
            sb1[r] = tb1[ti]; sb2[r] = tb2[ti]; sbj[r] = tj[ti];
        }
    }
    __syncthreads();

    // thread t owns point row t
    const int i = mt * 128 + t;
    const int bb = i >> 6, ni = i & 63;
    const int fi = ((bb * Cc + c) * Nn + ni) * DK;
    int bestj = sbj[t];

    // certify: bf16 screen error <= 2^-8*||x||*||k|| (+ slack)
    const float xnorm = g_xn[c * PPC + i];
    const float kmx = __uint_as_float(g_km[c]);
    const float bound = fmaf(0.0040f * kmx, xnorm, 2e-3f);
    const bool amb = (sb1[t] - sb2[t]) <= 2.0f * bound;

    unsigned m = __ballot_sync(0xffffffffu, amb);
    while (m) {
        int src = __ffs(m) - 1;
        m &= m - 1;
        int fs = __shfl_sync(0xffffffffu, fi, src);
        float xv[16];
        const float4* xr = (const float4*)(x + fs);
#pragma unroll
        for (int q = 0; q < 4; q++) {
            float4 v = xr[q];
            xv[4 * q] = v.x; xv[4 * q + 1] = v.y; xv[4 * q + 2] = v.z; xv[4 * q + 3] = v.w;
        }
        const float* kc0 = keys + (size_t)c * J * DK;
        float bs = -FLT_MAX; int bj = 0;
        for (int q = 0; q < 32; q++) {
            int j = q * 32 + lane;
            const float4* kr = (const float4*)(kc0 + (size_t)j * DK);
            float dot = 0.f, kk = 0.f;
#pragma unroll
            for (int u = 0; u < 4; u++) {
                float4 kv = kr[u];
                dot += xv[4 * u] * kv.x + xv[4 * u + 1] * kv.y + xv[4 * u + 2] * kv.z + xv[4 * u + 3] * kv.w;
                kk  += kv.x * kv.x + kv.y * kv.y + kv.z * kv.z + kv.w * kv.w;
            }
            float s = dot - 0.5f * kk;
            if (s > bs) { bs = s; bj = j; }  // ascending j, strict >
        }
#pragma unroll
        for (int off = 16; off > 0; off >>= 1) {
            float os = __shfl_down_sync(0xffffffffu, bs, off);
            int   oj = __shfl_down_sync(0xffffffffu, bj, off);
            if (os > bs || (os == bs && oj < bj)) { bs = os; bj = oj; }
        }
        int win = __shfl_sync(0xffffffffu, bj, 0);
        if (lane == src) bestj = win;
    }

    // Epilogue: qv gather + EMA atomics
    {
        const int j = bestj;
        const float4* vs = (const float4*)(values + (size_t)(c * J + j) * DK);
        float4* qd = (float4*)(out + OFF_QV + fi);
#pragma unroll
        for (int q = 0; q < 4; q++) qd[q] = vs[q];

        atomicAdd(out + OFF_CS + c * J + j, OMD);
        float* ka = out + OFF_KA + (size_t)(c * J + j) * DK;
        const float4* xr = (const float4*)(x + fi);
#pragma unroll
        for (int q = 0; q < 4; q++) {
            float4 v = xr[q];
            atomicAdd(ka + 4 * q,     OMD * v.x);
            atomicAdd(ka + 4 * q + 1, OMD * v.y);
            atomicAdd(ka + 4 * q + 2, OMD * v.z);
            atomicAdd(ka + 4 * q + 3, OMD * v.w);
        }
    }
}

// ---------------- kernel 2: finalize new_keys --------------------------------
__global__ __launch_bounds__(256) void k_final(float* __restrict__ out) {
    __shared__ float sred[256];
    const int c = blockIdx.x, t = threadIdx.x;
    const float* ncs = out + OFF_CS + c * J;

    float part = 0.f;
    for (int j = t; j < J; j += 256) part += ncs[j];
    sred[t] = part;
    __syncthreads();
    for (int s = 128; s > 0; s >>= 1) {
        if (t < s) sred[t] += sred[t + s];
        __syncthreads();
    }
    const float tot = sred[0];
    const float scale = tot / (tot + (float)J * EPSV);

    for (int j = t; j < J; j += 256) {
        float inv = 1.0f / ((ncs[j] + EPSV) * scale);
        const float4* ka = (const float4*)(out + OFF_KA + (size_t)(c * J + j) * DK);
        float4* nk = (float4*)(out + OFF_KEYS + (size_t)(c * J + j) * DK);
#pragma unroll
        for (int q = 0; q < 4; q++) {
            float4 v = ka[q];
            v.x *= inv; v.y *= inv; v.z *= inv; v.w *= inv;
            nk[q] = v;
        }
    }
}

extern "C" void kernel_launch(void* const* d_in, const int* in_sizes, int n_in,
                              void* d_out, int out_size) {
    const float* x        = (const float*)d_in[0];
    const float* keys     = (const float*)d_in[1];
    const float* values   = (const float*)d_in[2];
    const float* keys_avg = (const float*)d_in[3];
    const float* cs       = (const float*)d_in[4];
    float* out = (float*)d_out;

    k_prep<<<1024, 128>>>(x, keys, keys_avg, cs, out);
    k_screen<<<1024, 128>>>(x, keys, values, out);
    k_final<<<64, 256>>>(out);
}

// round 6
// speedup vs baseline: 2.8140x; 2.8140x over previous
#include <cuda_runtime.h>
#include <cuda_bf16.h>
#include <cstdint>
#include <cfloat>

// KeyValueBottleneck: b=32, C=64, n=64, dk=dv=16, J=1024
// out = concat(qv[2097152], new_keys[1048576], new_cluster_size[65536], new_keys_avg[1048576])

#define DECAY 0.95f
#define OMD   0.05f
#define EPSV  1e-5f

constexpr int Cc = 64, Nn = 64, DK = 16, J = 1024, PPC = 2048;
constexpr int OFF_QV   = 0;
constexpr int OFF_KEYS = 2097152;
constexpr int OFF_CS   = OFF_KEYS + Cc * J * DK;  // 3145728
constexpr int OFF_KA   = OFF_CS + Cc * J;         // 3211264

// ---------------- scratch (device globals; no allocation) --------------------
__device__ __nv_bfloat16 g_kb[(size_t)Cc * J * 32]; // 4 MB: [khi(16) | klo(16)]
__device__ float    g_kk[Cc * J];                   // -0.5*||k||^2 (fp32, exact bias)
__device__ unsigned g_km[Cc];                       // max ||k|| per channel (bits)

__device__ __forceinline__ uint32_t pkbf(float a, float b) {
    __nv_bfloat16 ha = __float2bfloat16(a), hb = __float2bfloat16(b);
    return (uint32_t)__bfloat16_as_ushort(ha) | ((uint32_t)__bfloat16_as_ushort(hb) << 16);
}

// classic tensor-core MMA: m16n8k16, bf16 x bf16 -> fp32 (sm_80+, works on sm_100)
__device__ __forceinline__ void mma16816(float* d, const uint32_t* a, const uint32_t* b) {
    asm volatile(
        "mma.sync.aligned.m16n8k16.row.col.f32.bf16.bf16.f32 "
        "{%0,%1,%2,%3}, {%4,%5,%6,%7}, {%8,%9}, {%0,%1,%2,%3};"
        : "+f"(d[0]), "+f"(d[1]), "+f"(d[2]), "+f"(d[3])
        : "r"(a[0]), "r"(a[1]), "r"(a[2]), "r"(a[3]), "r"(b[0]), "r"(b[1]));
}

// ---------------- kernel 0: EMA seed + key split-convert ---------------------
// grid 256 x 256 threads = 65536 = one thread per key row.
__global__ __launch_bounds__(256) void k_prep(const float* __restrict__ keys,
                                              const float* __restrict__ keys_avg,
                                              const float* __restrict__ cs,
                                              float* __restrict__ out) {
    const int tid = blockIdx.x * 256 + threadIdx.x;  // 0..65535

    // EMA seed: out_ka = DECAY*keys_avg (262144 f4), out_cs = DECAY*cs (16384 f4)
    {
        const float4* ka4 = (const float4*)keys_avg;
        float4* o4 = (float4*)out;
#pragma unroll
        for (int q = 0; q < 4; q++) {
            float4 v = ka4[tid + 65536 * q];
            v.x *= DECAY; v.y *= DECAY; v.z *= DECAY; v.w *= DECAY;
            o4[OFF_KA / 4 + tid + 65536 * q] = v;
        }
        if (tid < (Cc * J) / 4) {
            float4 u = ((const float4*)cs)[tid];
            u.x *= DECAY; u.y *= DECAY; u.z *= DECAY; u.w *= DECAY;
            o4[OFF_CS / 4 + tid] = u;
        }
    }

    // Key row tid: split into [khi | klo], bias, per-channel max norm
    {
        const int kc = tid >> 10;
        const float4* kr = (const float4*)(keys + (size_t)tid * DK);
        float kv[16], kk = 0.f;
#pragma unroll
        for (int q = 0; q < 4; q++) {
            float4 v = kr[q];
            kv[4 * q] = v.x; kv[4 * q + 1] = v.y; kv[4 * q + 2] = v.z; kv[4 * q + 3] = v.w;
            kk += v.x * v.x + v.y * v.y + v.z * v.z + v.w * v.w;
        }
        uint32_t w[16];
#pragma unroll
        for (int d = 0; d < 8; d++) {
            float a = kv[2 * d], b = kv[2 * d + 1];
            float ah = __bfloat162float(__float2bfloat16(a));
            float bh = __bfloat162float(__float2bfloat16(b));
            w[d]     = pkbf(a, b);            // khi
            w[8 + d] = pkbf(a - ah, b - bh);  // klo
        }
        uint4* dst = (uint4*)(g_kb + (size_t)tid * 32);
#pragma unroll
        for (int q = 0; q < 4; q++)
            dst[q] = make_uint4(w[4 * q], w[4 * q + 1], w[4 * q + 2], w[4 * q + 3]);
        g_kk[tid] = -0.5f * kk;
        atomicMax(&g_km[kc], __float_as_uint(sqrtf(kk)));
    }
}

// ---------------- kernel 1: split-bf16 HMMA screen + exact fp32 fallback -----
// grid = 1024 CTAs (c = bid>>4, mt = bid&15), 128 threads (4 warps).
// CTA: 128 points x 1024 keys. Screen = xhi.khi + xlo.khi + xhi.klo (fp32 accum)
// + exact fp32 bias. Error <= ||xlo||*||klo|| + accum slop ~ 1e-5*|x||k| + 1e-4.
__global__ __launch_bounds__(128) void k_screen(const float* __restrict__ x,
                                                const float* __restrict__ keys,
                                                const float* __restrict__ values,
                                                float* __restrict__ out) {
    // 80-byte padded rows -> conflict-free fragment LDS
    __shared__ __align__(16) unsigned char sA[128 * 80];    // [xhi|xlo] 10240 B
    __shared__ __align__(16) unsigned char sB[256 * 80];    // [khi|klo] 20480 B
    __shared__ float skk[J];
    __shared__ float sxn[128];
    __shared__ float sb1[128], sb2[128];
    __shared__ int   sbj[128];

    const int t = threadIdx.x, wid = t >> 5, lane = t & 31;
    const int c = blockIdx.x >> 4, mt = blockIdx.x & 15;
    const int lg = lane >> 2, lc = lane & 3;

    // this thread's point row (also reused for epilogue)
    const int i = mt * 128 + t;
    const int bb = i >> 6, ni = i & 63;
    const int fi = ((bb * Cc + c) * Nn + ni) * DK;

    // convert own x row -> sA (split hi/lo), compute ||x||
    {
        const float4* xr = (const float4*)(x + fi);
        float xv[16], n2 = 0.f;
#pragma unroll
        for (int q = 0; q < 4; q++) {
            float4 v = xr[q];
            xv[4 * q] = v.x; xv[4 * q + 1] = v.y; xv[4 * q + 2] = v.z; xv[4 * q + 3] = v.w;
            n2 += v.x * v.x + v.y * v.y + v.z * v.z + v.w * v.w;
        }
        uint32_t w[16];
#pragma unroll
        for (int d = 0; d < 8; d++) {
            float a = xv[2 * d], b = xv[2 * d + 1];
            float ah = __bfloat162float(__float2bfloat16(a));
            float bh = __bfloat162float(__float2bfloat16(b));
            w[d]     = pkbf(a, b);            // xhi
            w[8 + d] = pkbf(a - ah, b - bh);  // xlo
        }
        uint4* dst = (uint4*)(sA + t * 80);
#pragma unroll
        for (int q = 0; q < 4; q++)
            dst[q] = make_uint4(w[4 * q], w[4 * q + 1], w[4 * q + 2], w[4 * q + 3]);
        sxn[t] = sqrtf(n2);

        const float4* kk4 = (const float4*)(g_kk + c * J);
        ((float4*)skk)[t]       = kk4[t];
        ((float4*)skk)[t + 128] = kk4[t + 128];
    }
    __syncthreads();

    // A fragments register-resident: afr[mtile][hi/lo][4]
    uint32_t afr[2][2][4];
#pragma unroll
    for (int m = 0; m < 2; m++)
#pragma unroll
        for (int ks = 0; ks < 2; ks++) {
            int r0 = wid * 32 + m * 16 + lg;
            int bo = ks * 32 + lc * 4;
            afr[m][ks][0] = *(const uint32_t*)(sA + r0 * 80 + bo);
            afr[m][ks][1] = *(const uint32_t*)(sA + (r0 + 8) * 80 + bo);
            afr[m][ks][2] = *(const uint32_t*)(sA + r0 * 80 + bo + 16);
            afr[m][ks][3] = *(const uint32_t*)(sA + (r0 + 8) * 80 + bo + 16);
        }

    float tb1[4] = {-FLT_MAX, -FLT_MAX, -FLT_MAX, -FLT_MAX};
    float tb2[4] = {-FLT_MAX, -FLT_MAX, -FLT_MAX, -FLT_MAX};
    int   tj[4]  = {0, 0, 0, 0};

    for (int ch = 0; ch < 4; ch++) {
        // load B chunk (256 keys x [khi|klo] = 64 B rows)
        const uint4* src = (const uint4*)(g_kb + (size_t)(c * J + ch * 256) * 32);
#pragma unroll
        for (int v = t; v < 1024; v += 128) {
            int r = v >> 2, q = v & 3;
            *(uint4*)(sB + r * 80 + q * 16) = src[v];
        }
        __syncthreads();

#pragma unroll 4
        for (int jt = 0; jt < 32; jt++) {
            const int jbase = ch * 256 + jt * 8;
            const unsigned char* brow = sB + (jt * 8 + lg) * 80;
            uint32_t bh[2], bl[2];
            bh[0] = *(const uint32_t*)(brow + lc * 4);
            bh[1] = *(const uint32_t*)(brow + lc * 4 + 16);
            bl[0] = *(const uint32_t*)(brow + 32 + lc * 4);
            bl[1] = *(const uint32_t*)(brow + 32 + lc * 4 + 16);

            float d0[4] = {0.f, 0.f, 0.f, 0.f}, d1[4] = {0.f, 0.f, 0.f, 0.f};
            mma16816(d0, afr[0][0], bh);   // xhi.khi
            mma16816(d0, afr[0][1], bh);   // xlo.khi
            mma16816(d0, afr[0][0], bl);   // xhi.klo
            mma16816(d1, afr[1][0], bh);
            mma16816(d1, afr[1][1], bh);
            mma16816(d1, afr[1][0], bl);

            const int j0 = jbase + lc * 2;
            const float bias0 = skk[j0], bias1 = skk[j0 + 1];

#define UPD(ti, val, jj) { float s_ = (val); \
    if (s_ > tb1[ti]) { tb2[ti] = tb1[ti]; tb1[ti] = s_; tj[ti] = (jj); } \
    else if (s_ > tb2[ti]) tb2[ti] = s_; }
            UPD(0, d0[0] + bias0, j0); UPD(0, d0[1] + bias1, j0 + 1);
            UPD(1, d0[2] + bias0, j0); UPD(1, d0[3] + bias1, j0 + 1);
            UPD(2, d1[0] + bias0, j0); UPD(2, d1[1] + bias1, j0 + 1);
            UPD(3, d1[2] + bias0, j0); UPD(3, d1[3] + bias1, j0 + 1);
#undef UPD
        }
        __syncthreads();
    }

    // merge across the 4 lanes of each row-quad (disjoint col classes)
#pragma unroll
    for (int mask = 1; mask <= 2; mask <<= 1) {
#pragma unroll
        for (int ti = 0; ti < 4; ti++) {
            float ob1 = __shfl_xor_sync(0xffffffffu, tb1[ti], mask);
            float ob2 = __shfl_xor_sync(0xffffffffu, tb2[ti], mask);
            int   oj  = __shfl_xor_sync(0xffffffffu, tj[ti],  mask);
            if (ob1 > tb1[ti] || (ob1 == tb1[ti] && oj < tj[ti])) {
                tb2[ti] = fmaxf(tb1[ti], ob2);
                tb1[ti] = ob1; tj[ti] = oj;
            } else {
                tb2[ti] = fmaxf(tb2[ti], ob1);
            }
        }
    }
    if (lc == 0) {
#pragma unroll
        for (int ti = 0; ti < 4; ti++) {
            int r = wid * 32 + (ti >> 1) * 16 + (ti & 1) * 8 + lg;
            sb1[r] = tb1[ti]; sb2[r] = tb2[ti]; sbj[r] = tj[ti];
        }
    }
    __syncthreads();

    int bestj = sbj[t];

    // certify: screen error <= 2^-18*||x||*||k|| + fp32 accum slop
    const float kmx = __uint_as_float(g_km[c]);
    const float bound = fmaf(1e-5f * kmx, sxn[t], 1e-4f);
    const bool amb = (sb1[t] - sb2[t]) <= 2.0f * bound;

    unsigned m = __ballot_sync(0xffffffffu, amb);
    while (m) {
        int src = __ffs(m) - 1;
        m &= m - 1;
        int fs = __shfl_sync(0xffffffffu, fi, src);
        float xv[16];
        const float4* xr = (const float4*)(x + fs);
#pragma unroll
        for (int q = 0; q < 4; q++) {
            float4 v = xr[q];
            xv[4 * q] = v.x; xv[4 * q + 1] = v.y; xv[4 * q + 2] = v.z; xv[4 * q + 3] = v.w;
        }
        const float* kc0 = keys + (size_t)c * J * DK;
        float bs = -FLT_MAX; int bj = 0;
        for (int q = 0; q < 32; q++) {
            int j = q * 32 + lane;
            const float4* kr = (const float4*)(kc0 + (size_t)j * DK);
            float dot = 0.f, kk = 0.f;
#pragma unroll
            for (int u = 0; u < 4; u++) {
                float4 kv = kr[u];
                dot += xv[4 * u] * kv.x + xv[4 * u + 1] * kv.y + xv[4 * u + 2] * kv.z + xv[4 * u + 3] * kv.w;
                kk  += kv.x * kv.x + kv.y * kv.y + kv.z * kv.z + kv.w * kv.w;
            }
            float s = dot - 0.5f * kk;
            if (s > bs) { bs = s; bj = j; }  // ascending j, strict >
        }
#pragma unroll
        for (int off = 16; off > 0; off >>= 1) {
            float os = __shfl_down_sync(0xffffffffu, bs, off);
            int   oj = __shfl_down_sync(0xffffffffu, bj, off);
            if (os > bs || (os == bs && oj < bj)) { bs = os; bj = oj; }
        }
        int win = __shfl_sync(0xffffffffu, bj, 0);
        if (lane == src) bestj = win;
    }

    // Epilogue: qv gather + EMA atomics
    {
        const int j = bestj;
        const float4* vs = (const float4*)(values + (size_t)(c * J + j) * DK);
        float4* qd = (float4*)(out + OFF_QV + fi);
#pragma unroll
        for (int q = 0; q < 4; q++) qd[q] = vs[q];

        atomicAdd(out + OFF_CS + c * J + j, OMD);
        float* ka = out + OFF_KA + (size_t)(c * J + j) * DK;
        const float4* xr = (const float4*)(x + fi);
#pragma unroll
        for (int q = 0; q < 4; q++) {
            float4 v = xr[q];
            atomicAdd(ka + 4 * q,     OMD * v.x);
            atomicAdd(ka + 4 * q + 1, OMD * v.y);
            atomicAdd(ka + 4 * q + 2, OMD * v.z);
            atomicAdd(ka + 4 * q + 3, OMD * v.w);
        }
    }
}

// ---------------- kernel 2: finalize new_keys --------------------------------
__global__ __launch_bounds__(256) void k_final(float* __restrict__ out) {
    __shared__ float sred[256];
    const int c = blockIdx.x, t = threadIdx.x;
    const float* ncs = out + OFF_CS + c * J;

    float part = 0.f;
    for (int j = t; j < J; j += 256) part += ncs[j];
    sred[t] = part;
    __syncthreads();
    for (int s = 128; s > 0; s >>= 1) {
        if (t < s) sred[t] += sred[t + s];
        __syncthreads();
    }
    const float tot = sred[0];
    const float scale = tot / (tot + (float)J * EPSV);

    for (int j = t; j < J; j += 256) {
        float inv = 1.0f / ((ncs[j] + EPSV) * scale);
        const float4* ka = (const float4*)(out + OFF_KA + (size_t)(c * J + j) * DK);
        float4* nk = (float4*)(out + OFF_KEYS + (size_t)(c * J + j) * DK);
#pragma unroll
        for (int q = 0; q < 4; q++) {
            float4 v = ka[q];
            v.x *= inv; v.y *= inv; v.z *= inv; v.w *= inv;
            nk[q] = v;
        }
    }
}

extern "C" void kernel_launch(void* const* d_in, const int* in_sizes, int n_in,
                              void* d_out, int out_size) {
    const float* x        = (const float*)d_in[0];
    const float* keys     = (const float*)d_in[1];
    const float* values   = (const float*)d_in[2];
    const float* keys_avg = (const float*)d_in[3];
    const float* cs       = (const float*)d_in[4];
    float* out = (float*)d_out;

    k_prep<<<256, 256>>>(keys, keys_avg, cs, out);
    k_screen<<<1024, 128>>>(x, keys, values, out);
    k_final<<<64, 256>>>(out);
}

// round 7
// speedup vs baseline: 3.9642x; 1.4088x over previous
#include <cuda_runtime.h>
#include <cuda_bf16.h>
#include <cstdint>
#include <cfloat>

// KeyValueBottleneck: b=32, C=64, n=64, dk=dv=16, J=1024
// out = concat(qv[2097152], new_keys[1048576], new_cluster_size[65536], new_keys_avg[1048576])

#define DECAY 0.95f
#define OMD   0.05f
#define EPSV  1e-5f

constexpr int Cc = 64, Nn = 64, DK = 16, J = 1024, PPC = 2048;
constexpr int OFF_QV   = 0;
constexpr int OFF_KEYS = 2097152;
constexpr int OFF_CS   = OFF_KEYS + Cc * J * DK;  // 3145728
constexpr int OFF_KA   = OFF_CS + Cc * J;         // 3211264

// ---------------- scratch (device globals; no allocation) --------------------
__device__ __nv_bfloat16 g_kb[(size_t)Cc * J * 32]; // 4 MB: [khi(16) | klo(16)] per row
__device__ float    g_kk[Cc * J];                   // -0.5*||k||^2 (fp32, exact bias)
__device__ unsigned g_km[Cc];                       // max ||k|| per channel (bits)

__device__ __forceinline__ uint32_t pkbf(float a, float b) {
    __nv_bfloat16 ha = __float2bfloat16(a), hb = __float2bfloat16(b);
    return (uint32_t)__bfloat16_as_ushort(ha) | ((uint32_t)__bfloat16_as_ushort(hb) << 16);
}

// classic tensor-core MMA: m16n8k16, bf16 x bf16 -> fp32 (sm_80+)
__device__ __forceinline__ void mma16816(float* d, const uint32_t* a, const uint32_t* b) {
    asm volatile(
        "mma.sync.aligned.m16n8k16.row.col.f32.bf16.bf16.f32 "
        "{%0,%1,%2,%3}, {%4,%5,%6,%7}, {%8,%9}, {%0,%1,%2,%3};"
        : "+f"(d[0]), "+f"(d[1]), "+f"(d[2]), "+f"(d[3])
        : "r"(a[0]), "r"(a[1]), "r"(a[2]), "r"(a[3]), "r"(b[0]), "r"(b[1]));
}

__device__ __forceinline__ uint32_t smem_u32(const void* p) {
    uint32_t a;
    asm("{ .reg .u64 t; cvta.to.shared.u64 t, %1; cvt.u32.u64 %0, t; }" : "=r"(a) : "l"(p));
    return a;
}
__device__ __forceinline__ void cpasync16(uint32_t smem, const void* g) {
    asm volatile("cp.async.cg.shared.global [%0], [%1], 16;" :: "r"(smem), "l"(g));
}
#define CP_COMMIT() asm volatile("cp.async.commit_group;" ::: "memory")
#define CP_WAIT(n)  asm volatile("cp.async.wait_group %0;" :: "n"(n) : "memory")

// ---------------- kernel 0: EMA seed + key split-convert (fully parallel) ----
// grid 2112 x 256:
//   blocks [0,1024): out_ka = DECAY*keys_avg  (1 float4/thread)
//   blocks [1024,1088): out_cs = DECAY*cs     (1 float4/thread)
//   blocks [1088,2112): key rows, 4 threads/row (1 float4 of dims each)
__global__ __launch_bounds__(256) void k_prep(const float* __restrict__ keys,
                                              const float* __restrict__ keys_avg,
                                              const float* __restrict__ cs,
                                              float* __restrict__ out) {
    const int b = blockIdx.x, t = threadIdx.x;
    if (b < 1024) {
        int i = b * 256 + t;
        float4 v = ((const float4*)keys_avg)[i];
        v.x *= DECAY; v.y *= DECAY; v.z *= DECAY; v.w *= DECAY;
        ((float4*)out)[OFF_KA / 4 + i] = v;
        return;
    }
    if (b < 1088) {
        int i = (b - 1024) * 256 + t;
        float4 v = ((const float4*)cs)[i];
        v.x *= DECAY; v.y *= DECAY; v.z *= DECAY; v.w *= DECAY;
        ((float4*)out)[OFF_CS / 4 + i] = v;
        return;
    }
    // keys: tid2 in [0, 262144), row = tid2>>2 (65536 rows), q = tid2&3
    const int tid2 = (b - 1088) * 256 + t;
    const int row = tid2 >> 2, q = tid2 & 3, lane = t & 31;
    float4 kv = ((const float4*)keys)[row * 4 + q];
    float kk = kv.x * kv.x + kv.y * kv.y + kv.z * kv.z + kv.w * kv.w;
    // reduce kk over the 4 lanes sharing this row (lane%4 == q)
    kk += __shfl_xor_sync(0xffffffffu, kk, 1);
    kk += __shfl_xor_sync(0xffffffffu, kk, 2);
    // split-convert this thread's 4 dims
    float hx = __bfloat162float(__float2bfloat16(kv.x));
    float hy = __bfloat162float(__float2bfloat16(kv.y));
    float hz = __bfloat162float(__float2bfloat16(kv.z));
    float hw = __bfloat162float(__float2bfloat16(kv.w));
    uint2 whi = make_uint2(pkbf(kv.x, kv.y), pkbf(kv.z, kv.w));
    uint2 wlo = make_uint2(pkbf(kv.x - hx, kv.y - hy), pkbf(kv.z - hz, kv.w - hw));
    char* rowp = (char*)g_kb + (size_t)row * 64;
    *(uint2*)(rowp + q * 8)      = whi;
    *(uint2*)(rowp + 32 + q * 8) = wlo;
    if (q == 0) g_kk[row] = -0.5f * kk;
    // per-warp max norm -> 1 atomic (warp never straddles a channel: 1024%8==0)
    float mx = kk;
#pragma unroll
    for (int off = 16; off >= 4; off >>= 1)
        mx = fmaxf(mx, __shfl_xor_sync(0xffffffffu, mx, off));
    if (lane == 0) atomicMax(&g_km[row >> 10], __float_as_uint(sqrtf(mx)));
}

// ---------------- kernel 1: split-bf16 HMMA screen + exact fp32 fallback -----
// grid = 1024 CTAs (c = bid>>4, mt = bid&15), 256 threads (8 warps).
// CTA: 128 points x 1024 keys; warp w owns rows [w*16, w*16+16).
// Screen = xhi.khi + xlo.khi + xhi.klo (fp32 accum, bias in accumulator init).
// Error <= ||xlo||*||klo|| + accum slop ~ 1e-5*|x||k| + 1e-4.
__global__ __launch_bounds__(256) void k_screen(const float* __restrict__ x,
                                                const float* __restrict__ keys,
                                                const float* __restrict__ values,
                                                float* __restrict__ out) {
    __shared__ __align__(16) unsigned char sA[128 * 80];       // [xhi|xlo] rows
    __shared__ __align__(16) unsigned char sB[2][128 * 80];    // dbl-buf key chunks
    __shared__ float skk[J];
    __shared__ float sxn[128];
    __shared__ float sb1[128], sb2[128];
    __shared__ int   sbj[128];

    const int t = threadIdx.x, wid = t >> 5, lane = t & 31;
    const int c = blockIdx.x >> 4, mt = blockIdx.x & 15;
    const int lg = lane >> 2, lc = lane & 3;

    // convert x rows (threads 0..127, row t) + load skk (all 256)
    if (t < 128) {
        const int i0 = mt * 128 + t;
        const int fidx = (((i0 >> 6) * Cc + c) * Nn + (i0 & 63)) * DK;
        const float4* xr = (const float4*)(x + fidx);
        float xv[16], n2 = 0.f;
#pragma unroll
        for (int q = 0; q < 4; q++) {
            float4 v = xr[q];
            xv[4 * q] = v.x; xv[4 * q + 1] = v.y; xv[4 * q + 2] = v.z; xv[4 * q + 3] = v.w;
            n2 += v.x * v.x + v.y * v.y + v.z * v.z + v.w * v.w;
        }
        uint32_t w[16];
#pragma unroll
        for (int d = 0; d < 8; d++) {
            float a = xv[2 * d], bv = xv[2 * d + 1];
            float ah = __bfloat162float(__float2bfloat16(a));
            float bh = __bfloat162float(__float2bfloat16(bv));
            w[d]     = pkbf(a, bv);           // xhi
            w[8 + d] = pkbf(a - ah, bv - bh); // xlo
        }
        uint4* dst = (uint4*)(sA + t * 80);
#pragma unroll
        for (int q = 0; q < 4; q++)
            dst[q] = make_uint4(w[4 * q], w[4 * q + 1], w[4 * q + 2], w[4 * q + 3]);
        sxn[t] = sqrtf(n2);
    }
    ((float4*)skk)[t] = ((const float4*)(g_kk + c * J))[t];

    // prefetch key chunk 0 (128 rows x 64 B) via cp.async
    const uint32_t sb_base = smem_u32(sB);
    const char* kbase = (const char*)g_kb + (size_t)c * J * 64;
    {
        const char* src = kbase;
#pragma unroll
        for (int v = t; v < 512; v += 256) {
            int r = v >> 2, q = v & 3;
            cpasync16(sb_base + r * 80 + q * 16, src + r * 64 + q * 16);
        }
        CP_COMMIT();
    }
    __syncthreads();

    // A fragments register-resident: afr[hi/lo][4]  (1 m-tile: rows wid*16..+15)
    uint32_t afr[2][4];
#pragma unroll
    for (int ks = 0; ks < 2; ks++) {
        int r0 = wid * 16 + lg;
        int bo = ks * 32 + lc * 4;
        afr[ks][0] = *(const uint32_t*)(sA + r0 * 80 + bo);
        afr[ks][1] = *(const uint32_t*)(sA + (r0 + 8) * 80 + bo);
        afr[ks][2] = *(const uint32_t*)(sA + r0 * 80 + bo + 16);
        afr[ks][3] = *(const uint32_t*)(sA + (r0 + 8) * 80 + bo + 16);
    }

    float tb1[2] = {-FLT_MAX, -FLT_MAX};
    float tb2[2] = {-FLT_MAX, -FLT_MAX};
    int   tj[2]  = {0, 0};

    for (int ch = 0; ch < 8; ch++) {
        if (ch < 7) {  // prefetch next chunk into other buffer
            const char* src = kbase + (size_t)(ch + 1) * 128 * 64;
            uint32_t dstb = sb_base + ((ch + 1) & 1) * (128 * 80);
#pragma unroll
            for (int v = t; v < 512; v += 256) {
                int r = v >> 2, q = v & 3;
                cpasync16(dstb + r * 80 + q * 16, src + r * 64 + q * 16);
            }
            CP_COMMIT();
            CP_WAIT(1);
        } else {
            CP_WAIT(0);
        }
        __syncthreads();

        const unsigned char* buf = sB[ch & 1];
#pragma unroll 8
        for (int jt = 0; jt < 16; jt++) {
            const int j0 = ch * 128 + jt * 8 + lc * 2;
            const unsigned char* brow = buf + (jt * 8 + lg) * 80;
            uint32_t bh[2], bl[2];
            bh[0] = *(const uint32_t*)(brow + lc * 4);
            bh[1] = *(const uint32_t*)(brow + lc * 4 + 16);
            bl[0] = *(const uint32_t*)(brow + 32 + lc * 4);
            bl[1] = *(const uint32_t*)(brow + 32 + lc * 4 + 16);

            const float bias0 = skk[j0], bias1 = skk[j0 + 1];
            float d[4] = {bias0, bias1, bias0, bias1};
            mma16816(d, afr[0], bh);   // xhi.khi
            mma16816(d, afr[1], bh);   // xlo.khi
            mma16816(d, afr[0], bl);   // xhi.klo

#define UPD(ti, val, jj) { float s_ = (val); \
    if (s_ > tb1[ti]) { tb2[ti] = tb1[ti]; tb1[ti] = s_; tj[ti] = (jj); } \
    else if (s_ > tb2[ti]) tb2[ti] = s_; }
            UPD(0, d[0], j0); UPD(0, d[1], j0 + 1);
            UPD(1, d[2], j0); UPD(1, d[3], j0 + 1);
#undef UPD
        }
        __syncthreads();  // compute done before next prefetch overwrites buffer
    }

    // merge across the 4 lanes of each row-quad (disjoint col classes)
#pragma unroll
    for (int mask = 1; mask <= 2; mask <<= 1) {
#pragma unroll
        for (int ti = 0; ti < 2; ti++) {
            float ob1 = __shfl_xor_sync(0xffffffffu, tb1[ti], mask);
            float ob2 = __shfl_xor_sync(0xffffffffu, tb2[ti], mask);
            int   oj  = __shfl_xor_sync(0xffffffffu, tj[ti],  mask);
            if (ob1 > tb1[ti] || (ob1 == tb1[ti] && oj < tj[ti])) {
                tb2[ti] = fmaxf(tb1[ti], ob2);
                tb1[ti] = ob1; tj[ti] = oj;
            } else {
                tb2[ti] = fmaxf(tb2[ti], ob1);
            }
        }
    }
    if (lc == 0) {
#pragma unroll
        for (int ti = 0; ti < 2; ti++) {
            int r = wid * 16 + ti * 8 + lg;
            sb1[r] = tb1[ti]; sb2[r] = tb2[ti]; sbj[r] = tj[ti];
        }
    }
    __syncthreads();

    if (t >= 128) return;  // threads 0..127 own points

    const int i = mt * 128 + t;
    const int fi = (((i >> 6) * Cc + c) * Nn + (i & 63)) * DK;
    int bestj = sbj[t];

    // certify: screen error <= 2^-18*||x||*||k|| + fp32 accum slop
    const float kmx = __uint_as_float(g_km[c]);
    const float bound = fmaf(1e-5f * kmx, sxn[t], 1e-4f);
    const bool amb = (sb1[t] - sb2[t]) <= 2.0f * bound;

    unsigned m = __ballot_sync(0xffffffffu, amb);
    while (m) {
        int src = __ffs(m) - 1;
        m &= m - 1;
        int fs = __shfl_sync(0xffffffffu, fi, src);
        float xv[16];
        const float4* xr = (const float4*)(x + fs);
#pragma unroll
        for (int q = 0; q < 4; q++) {
            float4 v = xr[q];
            xv[4 * q] = v.x; xv[4 * q + 1] = v.y; xv[4 * q + 2] = v.z; xv[4 * q + 3] = v.w;
        }
        const float* kc0 = keys + (size_t)c * J * DK;
        float bs = -FLT_MAX; int bj = 0;
        for (int q = 0; q < 32; q++) {
            int j = q * 32 + lane;
            const float4* kr = (const float4*)(kc0 + (size_t)j * DK);
            float dot = 0.f, kk = 0.f;
#pragma unroll
            for (int u = 0; u < 4; u++) {
                float4 kv = kr[u];
                dot += xv[4 * u] * kv.x + xv[4 * u + 1] * kv.y + xv[4 * u + 2] * kv.z + xv[4 * u + 3] * kv.w;
                kk  += kv.x * kv.x + kv.y * kv.y + kv.z * kv.z + kv.w * kv.w;
            }
            float s = dot - 0.5f * kk;
            if (s > bs) { bs = s; bj = j; }  // ascending j, strict >
        }
#pragma unroll
        for (int off = 16; off > 0; off >>= 1) {
            float os = __shfl_down_sync(0xffffffffu, bs, off);
            int   oj = __shfl_down_sync(0xffffffffu, bj, off);
            if (os > bs || (os == bs && oj < bj)) { bs = os; bj = oj; }
        }
        int win = __shfl_sync(0xffffffffu, bj, 0);
        if (lane == src) bestj = win;
    }

    // Epilogue: qv gather + EMA atomics
    {
        const int j = bestj;
        const float4* vs = (const float4*)(values + (size_t)(c * J + j) * DK);
        float4* qd = (float4*)(out + OFF_QV + fi);
#pragma unroll
        for (int q = 0; q < 4; q++) qd[q] = vs[q];

        atomicAdd(out + OFF_CS + c * J + j, OMD);
        float* ka = out + OFF_KA + (size_t)(c * J + j) * DK;
        const float4* xr = (const float4*)(x + fi);
#pragma unroll
        for (int q = 0; q < 4; q++) {
            float4 v = xr[q];
            atomicAdd(ka + 4 * q,     OMD * v.x);
            atomicAdd(ka + 4 * q + 1, OMD * v.y);
            atomicAdd(ka + 4 * q + 2, OMD * v.z);
            atomicAdd(ka + 4 * q + 3, OMD * v.w);
        }
    }
}

// ---------------- kernel 2: finalize new_keys --------------------------------
__global__ __launch_bounds__(256) void k_final(float* __restrict__ out) {
    __shared__ float sred[256];
    const int c = blockIdx.x, t = threadIdx.x;
    const float* ncs = out + OFF_CS + c * J;

    float part = 0.f;
    for (int j = t; j < J; j += 256) part += ncs[j];
    sred[t] = part;
    __syncthreads();
    for (int s = 128; s > 0; s >>= 1) {
        if (t < s) sred[t] += sred[t + s];
        __syncthreads();
    }
    const float tot = sred[0];
    const float scale = tot / (tot + (float)J * EPSV);

    for (int j = t; j < J; j += 256) {
        float inv = 1.0f / ((ncs[j] + EPSV) * scale);
        const float4* ka = (const float4*)(out + OFF_KA + (size_t)(c * J + j) * DK);
        float4* nk = (float4*)(out + OFF_KEYS + (size_t)(c * J + j) * DK);
#pragma unroll
        for (int q = 0; q < 4; q++) {
            float4 v = ka[q];
            v.x *= inv; v.y *= inv; v.z *= inv; v.w *= inv;
            nk[q] = v;
        }
    }
}

extern "C" void kernel_launch(void* const* d_in, const int* in_sizes, int n_in,
                              void* d_out, int out_size) {
    const float* x        = (const float*)d_in[0];
    const float* keys     = (const float*)d_in[1];
    const float* values   = (const float*)d_in[2];
    const float* keys_avg = (const float*)d_in[3];
    const float* cs       = (const float*)d_in[4];
    float* out = (float*)d_out;

    k_prep<<<2112, 256>>>(keys, keys_avg, cs, out);
    k_screen<<<1024, 256>>>(x, keys, values, out);
    k_final<<<64, 256>>>(out);
}